// round 16
// baseline (speedup 1.0000x reference)
#include <cuda_runtime.h>

// Shapes (fixed by the problem): inputs [L,B,C,H,W] fp32, W [C,C] fp32
#define DL 4
#define DB 8
#define DC 256
#define DHW 4096             // 64*64
#define LBC (DL*DB*DC)       // 8192
#define VEC_PER_LBC 1024     // float4 per (l,b,c) row
#define CHB 4                // batches per chunk (67 MB, fits L2)
#define CH_ROWS (DL*CHB*DC)  // 4096 rows per chunk
#define A_BLOCKS (CHB * 8)   // 32 (8 d-groups of 32 per batch)

__device__ float g_gap[LBC];
__device__ float g_attn[LBC];

// ---------------------------------------------------------------------------
// G(b0): average-pool one row per block (16KB contiguous, MLP=4 — the config
// that measured 73% DRAM). Evict-normal fills feed M's reads via L2.
// ---------------------------------------------------------------------------
__global__ void __launch_bounds__(256) g_kernel(const float* __restrict__ in, int b0) {
    const int j  = blockIdx.x;               // 0..CH_ROWS-1
    const int l  = j >> 10;
    const int bi = (j >> 8) & (CHB - 1);
    const int c  = j & 255;
    const int g0 = (l * DB + b0 + bi) * DC + c;

    const float4* p = reinterpret_cast<const float4*>(in) + (size_t)g0 * VEC_PER_LBC;
    const int t = threadIdx.x;

    float4 v[4];
#pragma unroll
    for (int i = 0; i < 4; ++i) v[i] = p[i * 256 + t];

    cudaTriggerProgrammaticLaunchCompletion();   // let A (and the pipeline) ramp

    float s = 0.0f;
#pragma unroll
    for (int i = 0; i < 4; ++i) s += (v[i].x + v[i].y) + (v[i].z + v[i].w);

#pragma unroll
    for (int o = 16; o > 0; o >>= 1) s += __shfl_xor_sync(0xffffffffu, s, o);

    __shared__ float ws[8];
    if ((t & 31) == 0) ws[t >> 5] = s;
    __syncthreads();
    if (t < 8) {
        float r = ws[t];
#pragma unroll
        for (int o = 4; o > 0; o >>= 1) r += __shfl_xor_sync(0xffu, r, o);
        if (t == 0) g_gap[g0] = r * (1.0f / (float)DHW);
    }
}

// ---------------------------------------------------------------------------
// A(b0): attention for the chunk. 32 blocks: (bi, d-group of 32). Each block
// caches the batch's gap (4x256) in smem; each warp computes 4 output
// channels' scores via coalesced W-row loads + warp reduction, then softmax
// over L and writes g_attn.
// ---------------------------------------------------------------------------
__global__ void __launch_bounds__(256) a_kernel(const float* __restrict__ Wm, int b0) {
    const int bi = blockIdx.x >> 3;
    const int dg = blockIdx.x & 7;           // d-group of 32
    const int b  = b0 + bi;
    const int t  = threadIdx.x;
    const int warp = t >> 5, lane = t & 31;

    cudaGridDependencySynchronize();         // wait for G: g_gap ready

    __shared__ float gs[DL][DC];
    for (int i = t; i < DL * DC; i += 256) {
        const int l = i >> 8, c = i & 255;
        gs[l][c] = g_gap[(l * DB + b) * DC + c];
    }
    __syncthreads();

    cudaTriggerProgrammaticLaunchCompletion();

#pragma unroll
    for (int r = 0; r < 4; ++r) {
        const int d = dg * 32 + warp * 4 + r;
        float part[DL] = {0.f, 0.f, 0.f, 0.f};
#pragma unroll
        for (int k = 0; k < 8; ++k) {
            const int c = lane + 32 * k;
            const float wv = __ldg(&Wm[d * DC + c]);   // coalesced across lanes
#pragma unroll
            for (int l = 0; l < DL; ++l) part[l] = fmaf(wv, gs[l][c], part[l]);
        }
#pragma unroll
        for (int o = 16; o > 0; o >>= 1)
#pragma unroll
            for (int l = 0; l < DL; ++l) part[l] += __shfl_xor_sync(0xffffffffu, part[l], o);

        if (lane == 0) {
            float m = part[0];
#pragma unroll
            for (int l = 1; l < DL; ++l) m = fmaxf(m, part[l]);
            float e[DL], sum = 0.f;
#pragma unroll
            for (int l = 0; l < DL; ++l) { e[l] = __expf(part[l] - m); sum += e[l]; }
            const float inv = 1.0f / sum;
#pragma unroll
            for (int l = 0; l < DL; ++l)
                g_attn[(l * DB + b) * DC + d] = e[l] * inv;
        }
    }
}

// ---------------------------------------------------------------------------
// M(b0): pure stream. One row per block: prefetch 4 float4 (L2-hot, __ldcs),
// PDL-sync on A, load the single attn scalar, multiply, __stcs out.
// No smem, no __syncthreads, ~26 regs -> high occupancy.
// ---------------------------------------------------------------------------
__global__ void __launch_bounds__(256) m_kernel(const float* __restrict__ in,
                                                float* __restrict__ out, int b0) {
    const int w  = blockIdx.x;               // 0..CH_ROWS-1
    const int l0 = w >> 10;
    const int bi = (w >> 8) & (CHB - 1);
    const int d  = w & 255;
    const int g  = (l0 * DB + b0 + bi) * DC + d;
    const int t  = threadIdx.x;

    const size_t base = (size_t)g * VEC_PER_LBC;
    const float4* p = reinterpret_cast<const float4*>(in) + base;
    float4* q = reinterpret_cast<float4*>(out) + base;

    float4 v[4];
#pragma unroll
    for (int i = 0; i < 4; ++i) v[i] = __ldcs(&p[i * 256 + t]);

    cudaTriggerProgrammaticLaunchCompletion();   // let the next G ramp

    cudaGridDependencySynchronize();             // wait for A: g_attn ready
    const float a = g_attn[g];

#pragma unroll
    for (int i = 0; i < 4; ++i) {
        v[i].x *= a; v[i].y *= a; v[i].z *= a; v[i].w *= a;
        __stcs(&q[i * 256 + t], v[i]);
    }
}

// ---------------------------------------------------------------------------
template <typename... Args>
static inline void launch_pdl(void (*k)(Args...), int grid, Args... args) {
    cudaLaunchConfig_t cfg = {};
    cfg.gridDim = dim3(grid);
    cfg.blockDim = dim3(256);
    cfg.stream = 0;
    cudaLaunchAttribute attr[1];
    attr[0].id = cudaLaunchAttributeProgrammaticStreamSerialization;
    attr[0].val.programmaticStreamSerializationAllowed = 1;
    cfg.attrs = attr;
    cfg.numAttrs = 1;
    cudaLaunchKernelEx(&cfg, k, args...);
}

extern "C" void kernel_launch(void* const* d_in, const int* in_sizes, int n_in,
                              void* d_out, int out_size) {
    const float* in = (const float*)d_in[0];   // [L,B,C,H,W]
    const float* Wm = (const float*)d_in[1];   // [C,C]
    float* out = (float*)d_out;

    g_kernel<<<CH_ROWS, 256>>>(in, 0);                 // G0 (plain)
    launch_pdl(a_kernel, A_BLOCKS, Wm, 0);             // A0
    launch_pdl(m_kernel, CH_ROWS, in, out, 0);         // M0
    launch_pdl(g_kernel, CH_ROWS, in, (int)CHB);       // G1 (overlaps M0)
    launch_pdl(a_kernel, A_BLOCKS, Wm, (int)CHB);      // A1
    launch_pdl(m_kernel, CH_ROWS, in, out, (int)CHB);  // M1
}